// round 14
// baseline (speedup 1.0000x reference)
#include <cuda_runtime.h>
#include <math.h>

#define B_   8
#define T_   2048
#define E_   256
#define H_   8
#define DH_  32
#define M_   (B_ * T_)    // 16384 rows
#define N3_  (3 * E_)     // 768

// Scratch (allocation-free rule: __device__ globals)
__device__ float g_qkv[(size_t)M_ * N3_];   // [16384, 768]  q|k|v per row
__device__ float g_att[(size_t)M_ * E_];    // [16384, 256]  attention output (b,t,h,d)

// ---------------------------------------------------------------------------
// GEMM + bias: C[M,N] = A[M,K] @ W[K,N] + bias[N]
// Tile 64x64, BK=16, 256 threads, 4x4 microtile per thread.
// M,N,K all multiples of 64/16 for this problem -> no bounds checks.
// ---------------------------------------------------------------------------
__global__ void __launch_bounds__(256) sgemm_bias_kernel(
    const float* __restrict__ A, const float* __restrict__ W,
    const float* __restrict__ bias, float* __restrict__ C,
    int M, int N, int K)
{
    __shared__ float As[16][68];   // [k][m]
    __shared__ float Bs[16][68];   // [k][n]

    const int bm = blockIdx.y * 64;
    const int bn = blockIdx.x * 64;
    const int tid = threadIdx.x;
    const int tx = tid & 15;       // column group
    const int ty = tid >> 4;       // row group

    float acc[4][4] = {};

    for (int k0 = 0; k0 < K; k0 += 16) {
        #pragma unroll
        for (int i = 0; i < 4; i++) {
            int idx = tid + i * 256;
            int r = idx >> 4, c = idx & 15;          // 64 rows x 16 cols
            As[c][r] = A[(size_t)(bm + r) * K + (k0 + c)];
        }
        #pragma unroll
        for (int i = 0; i < 4; i++) {
            int idx = tid + i * 256;
            int r = idx >> 6, c = idx & 63;          // 16 rows x 64 cols
            Bs[r][c] = W[(size_t)(k0 + r) * N + (bn + c)];
        }
        __syncthreads();

        #pragma unroll
        for (int kk = 0; kk < 16; kk++) {
            float a[4], bv[4];
            #pragma unroll
            for (int i = 0; i < 4; i++) a[i]  = As[kk][ty * 4 + i];
            #pragma unroll
            for (int j = 0; j < 4; j++) bv[j] = Bs[kk][tx * 4 + j];
            #pragma unroll
            for (int i = 0; i < 4; i++)
                #pragma unroll
                for (int j = 0; j < 4; j++)
                    acc[i][j] = fmaf(a[i], bv[j], acc[i][j]);
        }
        __syncthreads();
    }

    #pragma unroll
    for (int i = 0; i < 4; i++) {
        int row = bm + ty * 4 + i;
        int col = bn + tx * 4;
        float4 r;
        r.x = acc[i][0] + bias[col + 0];
        r.y = acc[i][1] + bias[col + 1];
        r.z = acc[i][2] + bias[col + 2];
        r.w = acc[i][3] + bias[col + 3];
        *reinterpret_cast<float4*>(&C[(size_t)row * N + col]) = r;
    }
}

// ---------------------------------------------------------------------------
// RoPE in-place on q (cols [0,256)) and k (cols [256,512)) of g_qkv.
// One thread per (row, q/k, head, pair). freq_i = 10000^(-i/16), i in [0,16).
// angles up to 2047 rad -> use accurate sincosf (range reduction).
// ---------------------------------------------------------------------------
__global__ void __launch_bounds__(256) rope_kernel(float* __restrict__ qkv)
{
    const int total = M_ * 2 * H_ * (DH_ / 2);   // 4,194,304
    int idx = blockIdx.x * blockDim.x + threadIdx.x;
    if (idx >= total) return;

    int i = idx & 15;            // pair index
    int h = (idx >> 4) & 7;      // head
    int s = (idx >> 7) & 1;      // 0 = q, 1 = k
    int n = idx >> 8;            // row (b*T + t)
    int t = n & (T_ - 1);        // sequence position

    // 10000^(-i/16) = 2^(-i/16 * log2(10000))
    float freq = exp2f(-(float)i * (13.287712379549449f / 16.0f));
    float ang = (float)t * freq;
    float sn, cs;
    sincosf(ang, &sn, &cs);

    size_t base = (size_t)n * N3_ + s * E_ + h * DH_ + 2 * i;
    float x0 = qkv[base];
    float x1 = qkv[base + 1];
    qkv[base]     = x0 * cs - x1 * sn;
    qkv[base + 1] = x1 * cs + x0 * sn;
}

// ---------------------------------------------------------------------------
// Causal flash attention, fp32, Dh=32.
// Grid: (T/64, B*H). 256 threads: tx=tid&15 (cols), ty=tid>>4 (rows).
// Each thread: 4x4 of the 64x64 score tile; O fragment = 4 rows x 2 dims.
// Row softmax groups (fixed ty, 16 lanes) are contiguous within a warp ->
// shuffle reductions + __syncwarp between P-store and PV.
// Output layout: att[(b*T+t)*256 + h*32 + d]  (== bthd reshape).
// ---------------------------------------------------------------------------
__global__ void __launch_bounds__(256) flash_attn_kernel(
    const float* __restrict__ qkv, float* __restrict__ att)
{
    const int qtile = blockIdx.x;         // 0..31
    const int bh    = blockIdx.y;         // 0..63
    const int b = bh >> 3, h = bh & 7;
    const int tid = threadIdx.x;
    const int tx = tid & 15, ty = tid >> 4;

    __shared__ float Qs[64][32];
    __shared__ float Ks[64][33];
    __shared__ float Vs[64][32];
    __shared__ float Ps[64][68];

    const size_t row_base = (size_t)(b * T_) * N3_;
    const int qcol = h * DH_;
    const int kcol = E_ + h * DH_;
    const int vcol = 2 * E_ + h * DH_;

    // Load Q tile (coalesced: 32 floats per row = one 128B line)
    #pragma unroll
    for (int i = 0; i < 8; i++) {
        int idx = tid + i * 256;
        int r = idx >> 5, d = idx & 31;
        Qs[r][d] = qkv[row_base + (size_t)(qtile * 64 + r) * N3_ + qcol + d];
    }

    float m_i[4], l_i[4], o[4][2];
    #pragma unroll
    for (int i = 0; i < 4; i++) {
        m_i[i] = -1e30f; l_i[i] = 0.f; o[i][0] = 0.f; o[i][1] = 0.f;
    }

    const float scale = 0.17677669529663687f;  // 1/sqrt(32)

    for (int kt = 0; kt <= qtile; kt++) {
        __syncthreads();   // Vs/Ks free to overwrite (also covers Q-load on iter 0)
        #pragma unroll
        for (int i = 0; i < 8; i++) {
            int idx = tid + i * 256;
            int r = idx >> 5, d = idx & 31;
            size_t g = row_base + (size_t)(kt * 64 + r) * N3_;
            Ks[r][d] = qkv[g + kcol + d];
            Vs[r][d] = qkv[g + vcol + d];
        }
        __syncthreads();

        // S = Q K^T
        float s[4][4];
        #pragma unroll
        for (int i = 0; i < 4; i++)
            #pragma unroll
            for (int j = 0; j < 4; j++) s[i][j] = 0.f;

        #pragma unroll
        for (int d = 0; d < 32; d++) {
            float a[4], bb[4];
            #pragma unroll
            for (int i = 0; i < 4; i++) a[i]  = Qs[ty * 4 + i][d];
            #pragma unroll
            for (int j = 0; j < 4; j++) bb[j] = Ks[tx * 4 + j][d];
            #pragma unroll
            for (int i = 0; i < 4; i++)
                #pragma unroll
                for (int j = 0; j < 4; j++)
                    s[i][j] = fmaf(a[i], bb[j], s[i][j]);
        }

        // scale + causal mask (mask only on diagonal tile)
        if (kt == qtile) {
            #pragma unroll
            for (int i = 0; i < 4; i++) {
                int qr = ty * 4 + i;
                #pragma unroll
                for (int j = 0; j < 4; j++) {
                    int kc = tx * 4 + j;
                    s[i][j] = (kc <= qr) ? s[i][j] * scale : -1e30f;
                }
            }
        } else {
            #pragma unroll
            for (int i = 0; i < 4; i++)
                #pragma unroll
                for (int j = 0; j < 4; j++) s[i][j] *= scale;
        }

        // Online softmax, per-row (16-lane shuffle groups within a warp)
        #pragma unroll
        for (int i = 0; i < 4; i++) {
            float mx = fmaxf(fmaxf(s[i][0], s[i][1]), fmaxf(s[i][2], s[i][3]));
            #pragma unroll
            for (int off = 8; off >= 1; off >>= 1)
                mx = fmaxf(mx, __shfl_xor_sync(0xffffffffu, mx, off));
            float mnew  = fmaxf(m_i[i], mx);
            float alpha = __expf(m_i[i] - mnew);
            float ps = 0.f;
            #pragma unroll
            for (int j = 0; j < 4; j++) {
                float p = __expf(s[i][j] - mnew);
                Ps[ty * 4 + i][tx * 4 + j] = p;
                ps += p;
            }
            #pragma unroll
            for (int off = 8; off >= 1; off >>= 1)
                ps += __shfl_xor_sync(0xffffffffu, ps, off);
            m_i[i] = mnew;
            l_i[i] = l_i[i] * alpha + ps;
            o[i][0] *= alpha;
            o[i][1] *= alpha;
        }
        __syncwarp();   // Ps rows for this ty-group are produced/consumed in-warp

        // O += P V   (each thread: 4 rows x dims {2tx, 2tx+1})
        #pragma unroll 4
        for (int c = 0; c < 64; c++) {
            float2 v = *reinterpret_cast<const float2*>(&Vs[c][tx * 2]);
            #pragma unroll
            for (int i = 0; i < 4; i++) {
                float p = Ps[ty * 4 + i][c];
                o[i][0] = fmaf(p, v.x, o[i][0]);
                o[i][1] = fmaf(p, v.y, o[i][1]);
            }
        }
    }

    // Normalize and write (bthd layout)
    #pragma unroll
    for (int i = 0; i < 4; i++) {
        int qr = qtile * 64 + ty * 4 + i;
        float inv = 1.0f / l_i[i];
        size_t oidx = ((size_t)(b * T_ + qr)) * E_ + h * DH_ + tx * 2;
        att[oidx]     = o[i][0] * inv;
        att[oidx + 1] = o[i][1] * inv;
    }
}

// ---------------------------------------------------------------------------
// Launch
// ---------------------------------------------------------------------------
extern "C" void kernel_launch(void* const* d_in, const int* in_sizes, int n_in,
                              void* d_out, int out_size)
{
    const float* x    = (const float*)d_in[0];   // [8,2048,256]
    const float* Wqkv = (const float*)d_in[1];   // [256,768]
    const float* bqkv = (const float*)d_in[2];   // [768]
    const float* Wout = (const float*)d_in[3];   // [256,256]
    const float* bout = (const float*)d_in[4];   // [256]
    float* out = (float*)d_out;                  // [8,2048,256]
    (void)in_sizes; (void)n_in; (void)out_size;

    float* qkv = nullptr;
    float* att = nullptr;
    cudaGetSymbolAddress((void**)&qkv, g_qkv);
    cudaGetSymbolAddress((void**)&att, g_att);

    // 1) QKV projection + bias
    {
        dim3 grid(N3_ / 64, M_ / 64);   // (12, 256)
        sgemm_bias_kernel<<<grid, 256>>>(x, Wqkv, bqkv, qkv, M_, N3_, E_);
    }

    // 2) RoPE on q,k
    {
        int total = M_ * 2 * H_ * (DH_ / 2);
        rope_kernel<<<(total + 255) / 256, 256>>>(qkv);
    }

    // 3) Causal flash attention
    {
        dim3 grid(T_ / 64, B_ * H_);    // (32, 64)
        flash_attn_kernel<<<grid, 256>>>(qkv, att);
    }

    // 4) Output projection + bias
    {
        dim3 grid(E_ / 64, M_ / 64);    // (4, 256)
        sgemm_bias_kernel<<<grid, 256>>>(att, Wout, bout, out, M_, E_, E_);
    }
}

// round 15
// speedup vs baseline: 1.0017x; 1.0017x over previous
#include <cuda_runtime.h>
#include <math.h>

#define B_   8
#define T_   2048
#define E_   256
#define H_   8
#define DH_  32
#define M_   (B_ * T_)    // 16384 rows
#define N3_  (3 * E_)     // 768

// Scratch (allocation-free rule: __device__ globals)
__device__ float g_qkv[(size_t)M_ * N3_];   // [16384, 768]  q|k|v per row
__device__ float g_att[(size_t)M_ * E_];    // [16384, 256]  attention output (b,t,h,d)

// ---------------------------------------------------------------------------
// GEMM + bias: C[M,N] = A[M,K] @ W[K,N] + bias[N]
// Tile 64x64, BK=16, 256 threads, 4x4 microtile per thread.
// M,N,K all multiples of 64/16 for this problem -> no bounds checks.
// ---------------------------------------------------------------------------
__global__ void __launch_bounds__(256) sgemm_bias_kernel(
    const float* __restrict__ A, const float* __restrict__ W,
    const float* __restrict__ bias, float* __restrict__ C,
    int M, int N, int K)
{
    __shared__ float As[16][68];   // [k][m]
    __shared__ float Bs[16][68];   // [k][n]

    const int bm = blockIdx.y * 64;
    const int bn = blockIdx.x * 64;
    const int tid = threadIdx.x;
    const int tx = tid & 15;       // column group
    const int ty = tid >> 4;       // row group

    float acc[4][4] = {};

    for (int k0 = 0; k0 < K; k0 += 16) {
        #pragma unroll
        for (int i = 0; i < 4; i++) {
            int idx = tid + i * 256;
            int r = idx >> 4, c = idx & 15;          // 64 rows x 16 cols
            As[c][r] = A[(size_t)(bm + r) * K + (k0 + c)];
        }
        #pragma unroll
        for (int i = 0; i < 4; i++) {
            int idx = tid + i * 256;
            int r = idx >> 6, c = idx & 63;          // 16 rows x 64 cols
            Bs[r][c] = W[(size_t)(k0 + r) * N + (bn + c)];
        }
        __syncthreads();

        #pragma unroll
        for (int kk = 0; kk < 16; kk++) {
            float a[4], bv[4];
            #pragma unroll
            for (int i = 0; i < 4; i++) a[i]  = As[kk][ty * 4 + i];
            #pragma unroll
            for (int j = 0; j < 4; j++) bv[j] = Bs[kk][tx * 4 + j];
            #pragma unroll
            for (int i = 0; i < 4; i++)
                #pragma unroll
                for (int j = 0; j < 4; j++)
                    acc[i][j] = fmaf(a[i], bv[j], acc[i][j]);
        }
        __syncthreads();
    }

    #pragma unroll
    for (int i = 0; i < 4; i++) {
        int row = bm + ty * 4 + i;
        int col = bn + tx * 4;
        float4 r;
        r.x = acc[i][0] + bias[col + 0];
        r.y = acc[i][1] + bias[col + 1];
        r.z = acc[i][2] + bias[col + 2];
        r.w = acc[i][3] + bias[col + 3];
        *reinterpret_cast<float4*>(&C[(size_t)row * N + col]) = r;
    }
}

// ---------------------------------------------------------------------------
// RoPE in-place on q (cols [0,256)) and k (cols [256,512)) of g_qkv.
// One thread per (row, q/k, head, pair). freq_i = 10000^(-i/16), i in [0,16).
// angles up to 2047 rad -> use accurate sincosf (range reduction).
// ---------------------------------------------------------------------------
__global__ void __launch_bounds__(256) rope_kernel(float* __restrict__ qkv)
{
    const int total = M_ * 2 * H_ * (DH_ / 2);   // 4,194,304
    int idx = blockIdx.x * blockDim.x + threadIdx.x;
    if (idx >= total) return;

    int i = idx & 15;            // pair index
    int h = (idx >> 4) & 7;      // head
    int s = (idx >> 7) & 1;      // 0 = q, 1 = k
    int n = idx >> 8;            // row (b*T + t)
    int t = n & (T_ - 1);        // sequence position

    // 10000^(-i/16) = 2^(-i/16 * log2(10000))
    float freq = exp2f(-(float)i * (13.287712379549449f / 16.0f));
    float ang = (float)t * freq;
    float sn, cs;
    sincosf(ang, &sn, &cs);

    size_t base = (size_t)n * N3_ + s * E_ + h * DH_ + 2 * i;
    float x0 = qkv[base];
    float x1 = qkv[base + 1];
    qkv[base]     = x0 * cs - x1 * sn;
    qkv[base + 1] = x1 * cs + x0 * sn;
}

// ---------------------------------------------------------------------------
// Causal flash attention, fp32, Dh=32.
// Grid: (T/64, B*H). 256 threads: tx=tid&15 (cols), ty=tid>>4 (rows).
// Each thread: 4x4 of the 64x64 score tile; O fragment = 4 rows x 2 dims.
// Row softmax groups (fixed ty, 16 lanes) are contiguous within a warp ->
// shuffle reductions + __syncwarp between P-store and PV.
// Output layout: att[(b*T+t)*256 + h*32 + d]  (== bthd reshape).
// ---------------------------------------------------------------------------
__global__ void __launch_bounds__(256) flash_attn_kernel(
    const float* __restrict__ qkv, float* __restrict__ att)
{
    const int qtile = blockIdx.x;         // 0..31
    const int bh    = blockIdx.y;         // 0..63
    const int b = bh >> 3, h = bh & 7;
    const int tid = threadIdx.x;
    const int tx = tid & 15, ty = tid >> 4;

    __shared__ float Qs[64][32];
    __shared__ float Ks[64][33];
    __shared__ float Vs[64][32];
    __shared__ float Ps[64][68];

    const size_t row_base = (size_t)(b * T_) * N3_;
    const int qcol = h * DH_;
    const int kcol = E_ + h * DH_;
    const int vcol = 2 * E_ + h * DH_;

    // Load Q tile (coalesced: 32 floats per row = one 128B line)
    #pragma unroll
    for (int i = 0; i < 8; i++) {
        int idx = tid + i * 256;
        int r = idx >> 5, d = idx & 31;
        Qs[r][d] = qkv[row_base + (size_t)(qtile * 64 + r) * N3_ + qcol + d];
    }

    float m_i[4], l_i[4], o[4][2];
    #pragma unroll
    for (int i = 0; i < 4; i++) {
        m_i[i] = -1e30f; l_i[i] = 0.f; o[i][0] = 0.f; o[i][1] = 0.f;
    }

    const float scale = 0.17677669529663687f;  // 1/sqrt(32)

    for (int kt = 0; kt <= qtile; kt++) {
        __syncthreads();   // Vs/Ks free to overwrite (also covers Q-load on iter 0)
        #pragma unroll
        for (int i = 0; i < 8; i++) {
            int idx = tid + i * 256;
            int r = idx >> 5, d = idx & 31;
            size_t g = row_base + (size_t)(kt * 64 + r) * N3_;
            Ks[r][d] = qkv[g + kcol + d];
            Vs[r][d] = qkv[g + vcol + d];
        }
        __syncthreads();

        // S = Q K^T
        float s[4][4];
        #pragma unroll
        for (int i = 0; i < 4; i++)
            #pragma unroll
            for (int j = 0; j < 4; j++) s[i][j] = 0.f;

        #pragma unroll
        for (int d = 0; d < 32; d++) {
            float a[4], bb[4];
            #pragma unroll
            for (int i = 0; i < 4; i++) a[i]  = Qs[ty * 4 + i][d];
            #pragma unroll
            for (int j = 0; j < 4; j++) bb[j] = Ks[tx * 4 + j][d];
            #pragma unroll
            for (int i = 0; i < 4; i++)
                #pragma unroll
                for (int j = 0; j < 4; j++)
                    s[i][j] = fmaf(a[i], bb[j], s[i][j]);
        }

        // scale + causal mask (mask only on diagonal tile)
        if (kt == qtile) {
            #pragma unroll
            for (int i = 0; i < 4; i++) {
                int qr = ty * 4 + i;
                #pragma unroll
                for (int j = 0; j < 4; j++) {
                    int kc = tx * 4 + j;
                    s[i][j] = (kc <= qr) ? s[i][j] * scale : -1e30f;
                }
            }
        } else {
            #pragma unroll
            for (int i = 0; i < 4; i++)
                #pragma unroll
                for (int j = 0; j < 4; j++) s[i][j] *= scale;
        }

        // Online softmax, per-row (16-lane shuffle groups within a warp)
        #pragma unroll
        for (int i = 0; i < 4; i++) {
            float mx = fmaxf(fmaxf(s[i][0], s[i][1]), fmaxf(s[i][2], s[i][3]));
            #pragma unroll
            for (int off = 8; off >= 1; off >>= 1)
                mx = fmaxf(mx, __shfl_xor_sync(0xffffffffu, mx, off));
            float mnew  = fmaxf(m_i[i], mx);
            float alpha = __expf(m_i[i] - mnew);
            float ps = 0.f;
            #pragma unroll
            for (int j = 0; j < 4; j++) {
                float p = __expf(s[i][j] - mnew);
                Ps[ty * 4 + i][tx * 4 + j] = p;
                ps += p;
            }
            #pragma unroll
            for (int off = 8; off >= 1; off >>= 1)
                ps += __shfl_xor_sync(0xffffffffu, ps, off);
            m_i[i] = mnew;
            l_i[i] = l_i[i] * alpha + ps;
            o[i][0] *= alpha;
            o[i][1] *= alpha;
        }
        __syncwarp();   // Ps rows for this ty-group are produced/consumed in-warp

        // O += P V   (each thread: 4 rows x dims {2tx, 2tx+1})
        #pragma unroll 4
        for (int c = 0; c < 64; c++) {
            float2 v = *reinterpret_cast<const float2*>(&Vs[c][tx * 2]);
            #pragma unroll
            for (int i = 0; i < 4; i++) {
                float p = Ps[ty * 4 + i][c];
                o[i][0] = fmaf(p, v.x, o[i][0]);
                o[i][1] = fmaf(p, v.y, o[i][1]);
            }
        }
    }

    // Normalize and write (bthd layout)
    #pragma unroll
    for (int i = 0; i < 4; i++) {
        int qr = qtile * 64 + ty * 4 + i;
        float inv = 1.0f / l_i[i];
        size_t oidx = ((size_t)(b * T_ + qr)) * E_ + h * DH_ + tx * 2;
        att[oidx]     = o[i][0] * inv;
        att[oidx + 1] = o[i][1] * inv;
    }
}

// ---------------------------------------------------------------------------
// Launch
// ---------------------------------------------------------------------------
extern "C" void kernel_launch(void* const* d_in, const int* in_sizes, int n_in,
                              void* d_out, int out_size)
{
    const float* x    = (const float*)d_in[0];   // [8,2048,256]
    const float* Wqkv = (const float*)d_in[1];   // [256,768]
    const float* bqkv = (const float*)d_in[2];   // [768]
    const float* Wout = (const float*)d_in[3];   // [256,256]
    const float* bout = (const float*)d_in[4];   // [256]
    float* out = (float*)d_out;                  // [8,2048,256]
    (void)in_sizes; (void)n_in; (void)out_size;

    float* qkv = nullptr;
    float* att = nullptr;
    cudaGetSymbolAddress((void**)&qkv, g_qkv);
    cudaGetSymbolAddress((void**)&att, g_att);

    // 1) QKV projection + bias
    {
        dim3 grid(N3_ / 64, M_ / 64);   // (12, 256)
        sgemm_bias_kernel<<<grid, 256>>>(x, Wqkv, bqkv, qkv, M_, N3_, E_);
    }

    // 2) RoPE on q,k
    {
        int total = M_ * 2 * H_ * (DH_ / 2);
        rope_kernel<<<(total + 255) / 256, 256>>>(qkv);
    }

    // 3) Causal flash attention
    {
        dim3 grid(T_ / 64, B_ * H_);    // (32, 64)
        flash_attn_kernel<<<grid, 256>>>(qkv, att);
    }

    // 4) Output projection + bias
    {
        dim3 grid(E_ / 64, M_ / 64);    // (4, 256)
        sgemm_bias_kernel<<<grid, 256>>>(att, Wout, bout, out, M_, E_, E_);
    }
}

// round 16
// speedup vs baseline: 1.1963x; 1.1943x over previous
#include <cuda_runtime.h>
#include <math.h>

#define B_   8
#define T_   2048
#define E_   256
#define H_   8
#define DH_  32
#define M_   (B_ * T_)    // 16384 rows
#define N3_  (3 * E_)     // 768

// Scratch (allocation-free rule: __device__ globals)
__device__ float g_qkv[(size_t)M_ * N3_];   // [16384, 768]  q|k|v per row
__device__ float g_att[(size_t)M_ * E_];    // [16384, 256]  attention output (b,t,h,d)

// ---------------------------------------------------------------------------
// GEMM + bias: C[M,N] = A[M,K] @ W[K,N] + bias[N]   (unchanged, verified)
// ---------------------------------------------------------------------------
__global__ void __launch_bounds__(256) sgemm_bias_kernel(
    const float* __restrict__ A, const float* __restrict__ W,
    const float* __restrict__ bias, float* __restrict__ C,
    int M, int N, int K)
{
    __shared__ float As[16][68];   // [k][m]
    __shared__ float Bs[16][68];   // [k][n]

    const int bm = blockIdx.y * 64;
    const int bn = blockIdx.x * 64;
    const int tid = threadIdx.x;
    const int tx = tid & 15;
    const int ty = tid >> 4;

    float acc[4][4] = {};

    for (int k0 = 0; k0 < K; k0 += 16) {
        #pragma unroll
        for (int i = 0; i < 4; i++) {
            int idx = tid + i * 256;
            int r = idx >> 4, c = idx & 15;
            As[c][r] = A[(size_t)(bm + r) * K + (k0 + c)];
        }
        #pragma unroll
        for (int i = 0; i < 4; i++) {
            int idx = tid + i * 256;
            int r = idx >> 6, c = idx & 63;
            Bs[r][c] = W[(size_t)(k0 + r) * N + (bn + c)];
        }
        __syncthreads();

        #pragma unroll
        for (int kk = 0; kk < 16; kk++) {
            float a[4], bv[4];
            #pragma unroll
            for (int i = 0; i < 4; i++) a[i]  = As[kk][ty * 4 + i];
            #pragma unroll
            for (int j = 0; j < 4; j++) bv[j] = Bs[kk][tx * 4 + j];
            #pragma unroll
            for (int i = 0; i < 4; i++)
                #pragma unroll
                for (int j = 0; j < 4; j++)
                    acc[i][j] = fmaf(a[i], bv[j], acc[i][j]);
        }
        __syncthreads();
    }

    #pragma unroll
    for (int i = 0; i < 4; i++) {
        int row = bm + ty * 4 + i;
        int col = bn + tx * 4;
        float4 r;
        r.x = acc[i][0] + bias[col + 0];
        r.y = acc[i][1] + bias[col + 1];
        r.z = acc[i][2] + bias[col + 2];
        r.w = acc[i][3] + bias[col + 3];
        *reinterpret_cast<float4*>(&C[(size_t)row * N + col]) = r;
    }
}

// ---------------------------------------------------------------------------
// RoPE in-place on q, k of g_qkv (unchanged, verified)
// ---------------------------------------------------------------------------
__global__ void __launch_bounds__(256) rope_kernel(float* __restrict__ qkv)
{
    const int total = M_ * 2 * H_ * (DH_ / 2);
    int idx = blockIdx.x * blockDim.x + threadIdx.x;
    if (idx >= total) return;

    int i = idx & 15;
    int h = (idx >> 4) & 7;
    int s = (idx >> 7) & 1;
    int n = idx >> 8;
    int t = n & (T_ - 1);

    float freq = exp2f(-(float)i * (13.287712379549449f / 16.0f));
    float ang = (float)t * freq;
    float sn, cs;
    sincosf(ang, &sn, &cs);

    size_t base = (size_t)n * N3_ + s * E_ + h * DH_ + 2 * i;
    float x0 = qkv[base];
    float x1 = qkv[base + 1];
    qkv[base]     = x0 * cs - x1 * sn;
    qkv[base + 1] = x1 * cs + x0 * sn;
}

// ---------------------------------------------------------------------------
// Tensor-core flash attention, tf32x3 (== fp32 accuracy), Dh=32.
// CTA: 128 Q rows, 8 warps, 64-col KV tiles. Warp w owns rows [16w,16w+16).
// mma.m16n8k8 tf32 fragments:
//   A (row-major 16x8):  a0=(g,t) a1=(g+8,t) a2=(g,t+4) a3=(g+8,t+4)
//   B (col-major 8x8):   b0=(t,g) b1=(t+4,g)
//   C (16x8):            c0=(g,2t) c1=(g,2t+1) c2=(g+8,2t) c3=(g+8,2t+1)
// where g=lane>>2, t=lane&3.
// ---------------------------------------------------------------------------
__device__ __forceinline__ unsigned f2tf(float x) {
    unsigned u;
    asm("cvt.rna.tf32.f32 %0, %1;" : "=r"(u) : "f"(x));
    return u;
}

__device__ __forceinline__ void mma_tf32(
    float& d0, float& d1, float& d2, float& d3,
    unsigned a0, unsigned a1, unsigned a2, unsigned a3,
    unsigned b0, unsigned b1)
{
    asm("mma.sync.aligned.m16n8k8.row.col.f32.tf32.tf32.f32 "
        "{%0,%1,%2,%3}, {%4,%5,%6,%7}, {%8,%9}, {%0,%1,%2,%3};"
        : "+f"(d0), "+f"(d1), "+f"(d2), "+f"(d3)
        : "r"(a0), "r"(a1), "r"(a2), "r"(a3), "r"(b0), "r"(b1));
}

__global__ void __launch_bounds__(256, 2) flash_attn_tc_kernel(
    const float* __restrict__ qkv, float* __restrict__ att)
{
    __shared__ float sQ[128][36];  // stride 36: (4g+t) mod 32 conflict-free
    __shared__ float sK[64][36];   // stride 36: B-frag (g-major) conflict-free
    __shared__ float sV[64][40];   // stride 40: B-frag (t-major) conflict-free

    const int qb  = (int)gridDim.x - 1 - (int)blockIdx.x;  // heavy tiles first
    const int bh  = blockIdx.y;
    const int b   = bh >> 3, h = bh & 7;
    const int tid = threadIdx.x;
    const int w    = tid >> 5;
    const int lane = tid & 31;
    const int g    = lane >> 2;
    const int t    = lane & 3;

    const size_t rbase = (size_t)(b * T_) * N3_;
    const int qcol = h * DH_;
    const int kcol = E_ + h * DH_;
    const int vcol = 2 * E_ + h * DH_;

    // ---- stage Q tile (coalesced) ----
    #pragma unroll
    for (int i = 0; i < 16; i++) {
        int idx = tid + i * 256;             // 128*32 = 4096
        int r = idx >> 5, d = idx & 31;
        sQ[r][d] = qkv[rbase + (size_t)(qb * 128 + r) * N3_ + qcol + d];
    }
    __syncthreads();

    // ---- Q fragments (x scale), big+small split, cached for whole loop ----
    const float scale = 0.17677669529663687f;   // 1/sqrt(32)
    unsigned Qb[4][4], Qs[4][4];
    {
        int r0 = w * 16 + g;
        #pragma unroll
        for (int k = 0; k < 4; k++) {
            float v0 = sQ[r0    ][k * 8 + t    ] * scale;  // a0
            float v1 = sQ[r0 + 8][k * 8 + t    ] * scale;  // a1
            float v2 = sQ[r0    ][k * 8 + t + 4] * scale;  // a2
            float v3 = sQ[r0 + 8][k * 8 + t + 4] * scale;  // a3
            Qb[k][0] = f2tf(v0); Qs[k][0] = f2tf(v0 - __uint_as_float(Qb[k][0]));
            Qb[k][1] = f2tf(v1); Qs[k][1] = f2tf(v1 - __uint_as_float(Qb[k][1]));
            Qb[k][2] = f2tf(v2); Qs[k][2] = f2tf(v2 - __uint_as_float(Qb[k][2]));
            Qb[k][3] = f2tf(v3); Qs[k][3] = f2tf(v3 - __uint_as_float(Qb[k][3]));
        }
    }

    float m0 = -1e30f, m1 = -1e30f, l0 = 0.f, l1 = 0.f;
    float o[4][4];
    #pragma unroll
    for (int n = 0; n < 4; n++)
        o[n][0] = o[n][1] = o[n][2] = o[n][3] = 0.f;

    const int nkv = 2 * (qb + 1);
    for (int kt = 0; kt < nkv; kt++) {
        __syncthreads();   // previous tile's sK/sV reads done
        #pragma unroll
        for (int i = 0; i < 8; i++) {
            int idx = tid + i * 256;          // 64*32 = 2048
            int r = idx >> 5, d = idx & 31;
            size_t gr = rbase + (size_t)(kt * 64 + r) * N3_;
            sK[r][d] = qkv[gr + kcol + d];
            sV[r][d] = qkv[gr + vcol + d];
        }
        __syncthreads();

        // ---- S = (Q*scale) K^T  (tf32x3), warp tile 16x64 ----
        float s[8][4];
        #pragma unroll
        for (int n = 0; n < 8; n++) {
            s[n][0] = s[n][1] = s[n][2] = s[n][3] = 0.f;
            #pragma unroll
            for (int k = 0; k < 4; k++) {
                float k0f = sK[n * 8 + g][k * 8 + t];
                float k1f = sK[n * 8 + g][k * 8 + t + 4];
                unsigned kb0 = f2tf(k0f), kb1 = f2tf(k1f);
                unsigned ks0 = f2tf(k0f - __uint_as_float(kb0));
                unsigned ks1 = f2tf(k1f - __uint_as_float(kb1));
                mma_tf32(s[n][0], s[n][1], s[n][2], s[n][3],
                         Qb[k][0], Qb[k][1], Qb[k][2], Qb[k][3], kb0, kb1);
                mma_tf32(s[n][0], s[n][1], s[n][2], s[n][3],
                         Qb[k][0], Qb[k][1], Qb[k][2], Qb[k][3], ks0, ks1);
                mma_tf32(s[n][0], s[n][1], s[n][2], s[n][3],
                         Qs[k][0], Qs[k][1], Qs[k][2], Qs[k][3], kb0, kb1);
            }
        }

        // ---- causal mask (only last two tiles can touch the diagonal) ----
        if (kt >= 2 * qb) {
            int rowg = qb * 128 + w * 16 + g;
            #pragma unroll
            for (int n = 0; n < 8; n++) {
                int c = kt * 64 + n * 8 + 2 * t;
                if (c     > rowg    ) s[n][0] = -1e30f;
                if (c + 1 > rowg    ) s[n][1] = -1e30f;
                if (c     > rowg + 8) s[n][2] = -1e30f;
                if (c + 1 > rowg + 8) s[n][3] = -1e30f;
            }
        }

        // ---- online softmax: rows g (regs 0,1) and g+8 (regs 2,3) ----
        float mx0 = -1e30f, mx1 = -1e30f;
        #pragma unroll
        for (int n = 0; n < 8; n++) {
            mx0 = fmaxf(mx0, fmaxf(s[n][0], s[n][1]));
            mx1 = fmaxf(mx1, fmaxf(s[n][2], s[n][3]));
        }
        mx0 = fmaxf(mx0, __shfl_xor_sync(0xffffffffu, mx0, 1));
        mx0 = fmaxf(mx0, __shfl_xor_sync(0xffffffffu, mx0, 2));
        mx1 = fmaxf(mx1, __shfl_xor_sync(0xffffffffu, mx1, 1));
        mx1 = fmaxf(mx1, __shfl_xor_sync(0xffffffffu, mx1, 2));

        float M0 = fmaxf(m0, mx0), M1 = fmaxf(m1, mx1);
        float al0 = __expf(m0 - M0), al1 = __expf(m1 - M1);
        float sum0 = 0.f, sum1 = 0.f;
        #pragma unroll
        for (int n = 0; n < 8; n++) {
            s[n][0] = __expf(s[n][0] - M0);  sum0 += s[n][0];
            s[n][1] = __expf(s[n][1] - M0);  sum0 += s[n][1];
            s[n][2] = __expf(s[n][2] - M1);  sum1 += s[n][2];
            s[n][3] = __expf(s[n][3] - M1);  sum1 += s[n][3];
        }
        sum0 += __shfl_xor_sync(0xffffffffu, sum0, 1);
        sum0 += __shfl_xor_sync(0xffffffffu, sum0, 2);
        sum1 += __shfl_xor_sync(0xffffffffu, sum1, 1);
        sum1 += __shfl_xor_sync(0xffffffffu, sum1, 2);

        m0 = M0;  m1 = M1;
        l0 = l0 * al0 + sum0;
        l1 = l1 * al1 + sum1;
        #pragma unroll
        for (int n = 0; n < 4; n++) {
            o[n][0] *= al0;  o[n][1] *= al0;
            o[n][2] *= al1;  o[n][3] *= al1;
        }

        // ---- O += P V  (tf32x3); P A-frags built via in-warp shuffles ----
        const int srcA = (lane & 28) | (t >> 1);   // cols t   (C cols 2u,2u+1)
        const int srcB = srcA + 2;                 // cols t+4
        #pragma unroll
        for (int kk = 0; kk < 8; kk++) {
            float e0 = __shfl_sync(0xffffffffu, s[kk][0], srcA);
            float e1 = __shfl_sync(0xffffffffu, s[kk][1], srcA);
            float e2 = __shfl_sync(0xffffffffu, s[kk][2], srcA);
            float e3 = __shfl_sync(0xffffffffu, s[kk][3], srcA);
            float f0 = __shfl_sync(0xffffffffu, s[kk][0], srcB);
            float f1 = __shfl_sync(0xffffffffu, s[kk][1], srcB);
            float f2 = __shfl_sync(0xffffffffu, s[kk][2], srcB);
            float f3 = __shfl_sync(0xffffffffu, s[kk][3], srcB);
            float a0f = (t & 1) ? e1 : e0;   // P(g,    kk*8+t)
            float a1f = (t & 1) ? e3 : e2;   // P(g+8,  kk*8+t)
            float a2f = (t & 1) ? f1 : f0;   // P(g,    kk*8+t+4)
            float a3f = (t & 1) ? f3 : f2;   // P(g+8,  kk*8+t+4)
            unsigned Pb0 = f2tf(a0f), Pb1 = f2tf(a1f);
            unsigned Pb2 = f2tf(a2f), Pb3 = f2tf(a3f);
            unsigned Ps0 = f2tf(a0f - __uint_as_float(Pb0));
            unsigned Ps1 = f2tf(a1f - __uint_as_float(Pb1));
            unsigned Ps2 = f2tf(a2f - __uint_as_float(Pb2));
            unsigned Ps3 = f2tf(a3f - __uint_as_float(Pb3));

            #pragma unroll
            for (int n = 0; n < 4; n++) {
                float v0f = sV[kk * 8 + t    ][n * 8 + g];
                float v1f = sV[kk * 8 + t + 4][n * 8 + g];
                unsigned vb0 = f2tf(v0f), vb1 = f2tf(v1f);
                unsigned vs0 = f2tf(v0f - __uint_as_float(vb0));
                unsigned vs1 = f2tf(v1f - __uint_as_float(vb1));
                mma_tf32(o[n][0], o[n][1], o[n][2], o[n][3],
                         Pb0, Pb1, Pb2, Pb3, vb0, vb1);
                mma_tf32(o[n][0], o[n][1], o[n][2], o[n][3],
                         Pb0, Pb1, Pb2, Pb3, vs0, vs1);
                mma_tf32(o[n][0], o[n][1], o[n][2], o[n][3],
                         Ps0, Ps1, Ps2, Ps3, vb0, vb1);
            }
        }
    }

    // ---- normalize + write (bthd layout) ----
    float inv0 = 1.0f / l0;
    float inv1 = 1.0f / l1;
    int row0 = qb * 128 + w * 16 + g;
    size_t ob0 = ((size_t)(b * T_ + row0    )) * E_ + h * DH_;
    size_t ob1 = ((size_t)(b * T_ + row0 + 8)) * E_ + h * DH_;
    #pragma unroll
    for (int n = 0; n < 4; n++) {
        int c = n * 8 + 2 * t;
        *reinterpret_cast<float2*>(&att[ob0 + c]) =
            make_float2(o[n][0] * inv0, o[n][1] * inv0);
        *reinterpret_cast<float2*>(&att[ob1 + c]) =
            make_float2(o[n][2] * inv1, o[n][3] * inv1);
    }
}

// ---------------------------------------------------------------------------
// Launch
// ---------------------------------------------------------------------------
extern "C" void kernel_launch(void* const* d_in, const int* in_sizes, int n_in,
                              void* d_out, int out_size)
{
    const float* x    = (const float*)d_in[0];   // [8,2048,256]
    const float* Wqkv = (const float*)d_in[1];   // [256,768]
    const float* bqkv = (const float*)d_in[2];   // [768]
    const float* Wout = (const float*)d_in[3];   // [256,256]
    const float* bout = (const float*)d_in[4];   // [256]
    float* out = (float*)d_out;                  // [8,2048,256]
    (void)in_sizes; (void)n_in; (void)out_size;

    float* qkv = nullptr;
    float* att = nullptr;
    cudaGetSymbolAddress((void**)&qkv, g_qkv);
    cudaGetSymbolAddress((void**)&att, g_att);

    // 1) QKV projection + bias
    {
        dim3 grid(N3_ / 64, M_ / 64);   // (12, 256)
        sgemm_bias_kernel<<<grid, 256>>>(x, Wqkv, bqkv, qkv, M_, N3_, E_);
    }

    // 2) RoPE on q,k
    {
        int total = M_ * 2 * H_ * (DH_ / 2);
        rope_kernel<<<(total + 255) / 256, 256>>>(qkv);
    }

    // 3) Causal flash attention (tensor cores, tf32x3)
    {
        dim3 grid(T_ / 128, B_ * H_);   // (16, 64)
        flash_attn_tc_kernel<<<grid, 256>>>(qkv, att);
    }

    // 4) Output projection + bias
    {
        dim3 grid(E_ / 64, M_ / 64);    // (4, 256)
        sgemm_bias_kernel<<<grid, 256>>>(att, Wout, bout, out, M_, E_, E_);
    }
}

// round 17
// speedup vs baseline: 1.7231x; 1.4404x over previous
#include <cuda_runtime.h>
#include <math.h>

#define B_   8
#define T_   2048
#define E_   256
#define H_   8
#define DH_  32
#define M_   (B_ * T_)    // 16384 rows
#define N3_  (3 * E_)     // 768

// Scratch (allocation-free rule: __device__ globals)
__device__ float  g_qkv[(size_t)M_ * N3_];   // [16384, 768]  q|k|v per row
__device__ float  g_att[(size_t)M_ * E_];    // [16384, 256]  attention out (b,t,h,d)
__device__ float2 g_rot[T_][16];             // per (t, pair): (cos, sin)

// ---------------------------------------------------------------------------
// GEMM + bias: C[M,N] = A[M,K] @ W[K,N] + bias[N]   (unchanged, verified)
// ---------------------------------------------------------------------------
__global__ void __launch_bounds__(256) sgemm_bias_kernel(
    const float* __restrict__ A, const float* __restrict__ W,
    const float* __restrict__ bias, float* __restrict__ C,
    int M, int N, int K)
{
    __shared__ float As[16][68];
    __shared__ float Bs[16][68];

    const int bm = blockIdx.y * 64;
    const int bn = blockIdx.x * 64;
    const int tid = threadIdx.x;
    const int tx = tid & 15;
    const int ty = tid >> 4;

    float acc[4][4] = {};

    for (int k0 = 0; k0 < K; k0 += 16) {
        #pragma unroll
        for (int i = 0; i < 4; i++) {
            int idx = tid + i * 256;
            int r = idx >> 4, c = idx & 15;
            As[c][r] = A[(size_t)(bm + r) * K + (k0 + c)];
        }
        #pragma unroll
        for (int i = 0; i < 4; i++) {
            int idx = tid + i * 256;
            int r = idx >> 6, c = idx & 63;
            Bs[r][c] = W[(size_t)(k0 + r) * N + (bn + c)];
        }
        __syncthreads();

        #pragma unroll
        for (int kk = 0; kk < 16; kk++) {
            float a[4], bv[4];
            #pragma unroll
            for (int i = 0; i < 4; i++) a[i]  = As[kk][ty * 4 + i];
            #pragma unroll
            for (int j = 0; j < 4; j++) bv[j] = Bs[kk][tx * 4 + j];
            #pragma unroll
            for (int i = 0; i < 4; i++)
                #pragma unroll
                for (int j = 0; j < 4; j++)
                    acc[i][j] = fmaf(a[i], bv[j], acc[i][j]);
        }
        __syncthreads();
    }

    #pragma unroll
    for (int i = 0; i < 4; i++) {
        int row = bm + ty * 4 + i;
        int col = bn + tx * 4;
        float4 r;
        r.x = acc[i][0] + bias[col + 0];
        r.y = acc[i][1] + bias[col + 1];
        r.z = acc[i][2] + bias[col + 2];
        r.w = acc[i][3] + bias[col + 3];
        *reinterpret_cast<float4*>(&C[(size_t)row * N + col]) = r;
    }
}

// ---------------------------------------------------------------------------
// RoPE cos/sin table: 2048 positions x 16 pairs (accurate sincosf, once)
// ---------------------------------------------------------------------------
__global__ void __launch_bounds__(256) rope_table_kernel()
{
    int idx = blockIdx.x * blockDim.x + threadIdx.x;   // 32768 total
    if (idx >= T_ * 16) return;
    int t = idx >> 4;
    int i = idx & 15;
    float freq = exp2f(-(float)i * (13.287712379549449f / 16.0f));
    float ang = (float)t * freq;
    float sn, cs;
    sincosf(ang, &sn, &cs);
    g_rot[t][i] = make_float2(cs, sn);
}

// ---------------------------------------------------------------------------
// RoPE in-place on q, k of g_qkv via table (pure bandwidth)
// ---------------------------------------------------------------------------
__global__ void __launch_bounds__(256) rope_kernel(float* __restrict__ qkv)
{
    const int total = M_ * 2 * H_ * (DH_ / 2);   // 4,194,304
    int idx = blockIdx.x * blockDim.x + threadIdx.x;
    if (idx >= total) return;

    int i = idx & 15;
    int h = (idx >> 4) & 7;
    int s = (idx >> 7) & 1;
    int n = idx >> 8;
    int t = n & (T_ - 1);

    float2 cs = g_rot[t][i];

    size_t base = (size_t)n * N3_ + s * E_ + h * DH_ + 2 * i;
    float2 x = *reinterpret_cast<float2*>(&qkv[base]);
    float2 y;
    y.x = x.x * cs.x - x.y * cs.y;
    y.y = x.y * cs.x + x.x * cs.y;
    *reinterpret_cast<float2*>(&qkv[base]) = y;
}

// ---------------------------------------------------------------------------
// Tensor-core flash attention, Dh=32.
// QK^T: 1-pass tf32 (Qb x Kb).  PV: 2-pass (Pb·Vb + Ps·Vb).
// CTA: 128 Q rows, 8 warps x (16 rows x 64-col KV tile).
// K/V converted to tf32 ONCE per CTA per tile into packed smem layouts.
// mma.m16n8k8 fragments (g=lane>>2, t=lane&3):
//   A row-major 16x8: a0=(g,t) a1=(g+8,t) a2=(g,t+4) a3=(g+8,t+4)
//   B col-major 8x8:  b0=(t,g) b1=(t+4,g)
//   C 16x8: c0=(g,2t) c1=(g,2t+1) c2=(g+8,2t) c3=(g+8,2t+1)
// ---------------------------------------------------------------------------
__device__ __forceinline__ unsigned f2tf(float x) {
    unsigned u;
    asm("cvt.rna.tf32.f32 %0, %1;" : "=r"(u) : "f"(x));
    return u;
}

__device__ __forceinline__ void mma_tf32(
    float& d0, float& d1, float& d2, float& d3,
    unsigned a0, unsigned a1, unsigned a2, unsigned a3,
    unsigned b0, unsigned b1)
{
    asm("mma.sync.aligned.m16n8k8.row.col.f32.tf32.tf32.f32 "
        "{%0,%1,%2,%3}, {%4,%5,%6,%7}, {%8,%9}, {%0,%1,%2,%3};"
        : "+f"(d0), "+f"(d1), "+f"(d2), "+f"(d3)
        : "r"(a0), "r"(a1), "r"(a2), "r"(a3), "r"(b0), "r"(b1));
}

__global__ void __launch_bounds__(256, 2) flash_attn_tc_kernel(
    const float* __restrict__ qkv, float* __restrict__ att)
{
    __shared__ float    sQ[128][34];    // raw Q tile (prologue only)
    __shared__ unsigned KbP[64][36];    // K tf32, fragment-permuted
    __shared__ unsigned VbP[32][70];    // V tf32, pair-packed per head-dim col

    const int qb  = (int)gridDim.x - 1 - (int)blockIdx.x;  // heavy tiles first
    const int bh  = blockIdx.y;
    const int b   = bh >> 3, h = bh & 7;
    const int tid = threadIdx.x;
    const int w    = tid >> 5;
    const int lane = tid & 31;
    const int g    = lane >> 2;
    const int t    = lane & 3;

    const size_t rbase = (size_t)(b * T_) * N3_;
    const int qcol = h * DH_;
    const int kcol = E_ + h * DH_;
    const int vcol = 2 * E_ + h * DH_;

    // ---- stage Q tile (coalesced) ----
    #pragma unroll
    for (int i = 0; i < 16; i++) {
        int idx = tid + i * 256;
        int r = idx >> 5, d = idx & 31;
        sQ[r][d] = qkv[rbase + (size_t)(qb * 128 + r) * N3_ + qcol + d];
    }
    __syncthreads();

    // ---- Q fragments (x scale), big-only, cached for whole loop ----
    const float scale = 0.17677669529663687f;   // 1/sqrt(32)
    unsigned Qb[4][4];
    {
        int r0 = w * 16 + g;
        #pragma unroll
        for (int k = 0; k < 4; k++) {
            Qb[k][0] = f2tf(sQ[r0    ][k * 8 + t    ] * scale);
            Qb[k][1] = f2tf(sQ[r0 + 8][k * 8 + t    ] * scale);
            Qb[k][2] = f2tf(sQ[r0    ][k * 8 + t + 4] * scale);
            Qb[k][3] = f2tf(sQ[r0 + 8][k * 8 + t + 4] * scale);
        }
    }

    // ---- hoisted conversion-phase indices ----
    // K element: row r = r0 + 8i, col d (fixed per thread)
    const int cd  = tid & 31;            // K col / V col (head-dim)
    const int r0  = tid >> 5;            // 0..7
    const int kk_ = cd >> 3, tt_ = cd & 7;
    const int kt2 = tt_ & 3, kh = tt_ >> 2;
    const int kdst = kt2 * 8 + 2 * kk_ + kh;        // KbP permuted col
    const int vt2 = r0 & 3, vh = r0 >> 2;           // V: r&7 == r0

    float m0 = -1e30f, m1 = -1e30f, l0 = 0.f, l1 = 0.f;
    float o[4][4];
    #pragma unroll
    for (int n = 0; n < 4; n++)
        o[n][0] = o[n][1] = o[n][2] = o[n][3] = 0.f;

    const int nkv = 2 * (qb + 1);
    for (int kt = 0; kt < nkv; kt++) {
        __syncthreads();   // previous tile's KbP/VbP reads done
        // ---- cooperative load + tf32 convert + permuted store ----
        #pragma unroll
        for (int i = 0; i < 8; i++) {
            int r = r0 + 8 * i;
            size_t gr = rbase + (size_t)(kt * 64 + r) * N3_;
            KbP[r][kdst] = f2tf(qkv[gr + kcol + cd]);
            VbP[cd][(i * 4 + vt2) * 2 + vh] = f2tf(qkv[gr + vcol + cd]);
        }
        __syncthreads();

        // ---- S = (Q*scale) K^T  (1-pass tf32), warp tile 16x64 ----
        float s[8][4];
        #pragma unroll
        for (int n = 0; n < 8; n++) {
            s[n][0] = s[n][1] = s[n][2] = s[n][3] = 0.f;
            const uint4* kp = reinterpret_cast<const uint4*>(&KbP[n * 8 + g][t * 8]);
            uint4 kA = kp[0];   // k=0: (x,y)  k=1: (z,w)
            uint4 kB = kp[1];   // k=2: (x,y)  k=3: (z,w)
            mma_tf32(s[n][0], s[n][1], s[n][2], s[n][3],
                     Qb[0][0], Qb[0][1], Qb[0][2], Qb[0][3], kA.x, kA.y);
            mma_tf32(s[n][0], s[n][1], s[n][2], s[n][3],
                     Qb[1][0], Qb[1][1], Qb[1][2], Qb[1][3], kA.z, kA.w);
            mma_tf32(s[n][0], s[n][1], s[n][2], s[n][3],
                     Qb[2][0], Qb[2][1], Qb[2][2], Qb[2][3], kB.x, kB.y);
            mma_tf32(s[n][0], s[n][1], s[n][2], s[n][3],
                     Qb[3][0], Qb[3][1], Qb[3][2], Qb[3][3], kB.z, kB.w);
        }

        // ---- causal mask (only the last two tiles touch the diagonal) ----
        if (kt >= 2 * qb) {
            int rowg = qb * 128 + w * 16 + g;
            #pragma unroll
            for (int n = 0; n < 8; n++) {
                int c = kt * 64 + n * 8 + 2 * t;
                if (c     > rowg    ) s[n][0] = -1e30f;
                if (c + 1 > rowg    ) s[n][1] = -1e30f;
                if (c     > rowg + 8) s[n][2] = -1e30f;
                if (c + 1 > rowg + 8) s[n][3] = -1e30f;
            }
        }

        // ---- online softmax: rows g (regs 0,1) and g+8 (regs 2,3) ----
        float mx0 = -1e30f, mx1 = -1e30f;
        #pragma unroll
        for (int n = 0; n < 8; n++) {
            mx0 = fmaxf(mx0, fmaxf(s[n][0], s[n][1]));
            mx1 = fmaxf(mx1, fmaxf(s[n][2], s[n][3]));
        }
        mx0 = fmaxf(mx0, __shfl_xor_sync(0xffffffffu, mx0, 1));
        mx0 = fmaxf(mx0, __shfl_xor_sync(0xffffffffu, mx0, 2));
        mx1 = fmaxf(mx1, __shfl_xor_sync(0xffffffffu, mx1, 1));
        mx1 = fmaxf(mx1, __shfl_xor_sync(0xffffffffu, mx1, 2));

        float M0 = fmaxf(m0, mx0), M1 = fmaxf(m1, mx1);
        float al0 = __expf(m0 - M0), al1 = __expf(m1 - M1);
        float sum0 = 0.f, sum1 = 0.f;
        #pragma unroll
        for (int n = 0; n < 8; n++) {
            s[n][0] = __expf(s[n][0] - M0);  sum0 += s[n][0];
            s[n][1] = __expf(s[n][1] - M0);  sum0 += s[n][1];
            s[n][2] = __expf(s[n][2] - M1);  sum1 += s[n][2];
            s[n][3] = __expf(s[n][3] - M1);  sum1 += s[n][3];
        }
        sum0 += __shfl_xor_sync(0xffffffffu, sum0, 1);
        sum0 += __shfl_xor_sync(0xffffffffu, sum0, 2);
        sum1 += __shfl_xor_sync(0xffffffffu, sum1, 1);
        sum1 += __shfl_xor_sync(0xffffffffu, sum1, 2);

        m0 = M0;  m1 = M1;
        l0 = l0 * al0 + sum0;
        l1 = l1 * al1 + sum1;
        #pragma unroll
        for (int n = 0; n < 4; n++) {
            o[n][0] *= al0;  o[n][1] *= al0;
            o[n][2] *= al1;  o[n][3] *= al1;
        }

        // ---- O += P V  (Pb·Vb + Ps·Vb); P A-frags via in-warp shuffles ----
        const int srcA = (lane & 28) | (t >> 1);   // cols t
        const int srcB = srcA + 2;                 // cols t+4
        #pragma unroll
        for (int kk = 0; kk < 8; kk++) {
            float e0 = __shfl_sync(0xffffffffu, s[kk][0], srcA);
            float e1 = __shfl_sync(0xffffffffu, s[kk][1], srcA);
            float e2 = __shfl_sync(0xffffffffu, s[kk][2], srcA);
            float e3 = __shfl_sync(0xffffffffu, s[kk][3], srcA);
            float f0 = __shfl_sync(0xffffffffu, s[kk][0], srcB);
            float f1 = __shfl_sync(0xffffffffu, s[kk][1], srcB);
            float f2 = __shfl_sync(0xffffffffu, s[kk][2], srcB);
            float f3 = __shfl_sync(0xffffffffu, s[kk][3], srcB);
            float a0f = (t & 1) ? e1 : e0;   // P(g,    kk*8+t)
            float a1f = (t & 1) ? e3 : e2;   // P(g+8,  kk*8+t)
            float a2f = (t & 1) ? f1 : f0;   // P(g,    kk*8+t+4)
            float a3f = (t & 1) ? f3 : f2;   // P(g+8,  kk*8+t+4)
            unsigned Pb0 = f2tf(a0f), Pb1 = f2tf(a1f);
            unsigned Pb2 = f2tf(a2f), Pb3 = f2tf(a3f);
            unsigned Ps0 = f2tf(a0f - __uint_as_float(Pb0));
            unsigned Ps1 = f2tf(a1f - __uint_as_float(Pb1));
            unsigned Ps2 = f2tf(a2f - __uint_as_float(Pb2));
            unsigned Ps3 = f2tf(a3f - __uint_as_float(Pb3));

            #pragma unroll
            for (int n = 0; n < 4; n++) {
                uint2 vb = *reinterpret_cast<const uint2*>(
                    &VbP[n * 8 + g][(kk * 4 + t) * 2]);
                mma_tf32(o[n][0], o[n][1], o[n][2], o[n][3],
                         Pb0, Pb1, Pb2, Pb3, vb.x, vb.y);
                mma_tf32(o[n][0], o[n][1], o[n][2], o[n][3],
                         Ps0, Ps1, Ps2, Ps3, vb.x, vb.y);
            }
        }
    }

    // ---- normalize + write (bthd layout) ----
    float inv0 = 1.0f / l0;
    float inv1 = 1.0f / l1;
    int row0 = qb * 128 + w * 16 + g;
    size_t ob0 = ((size_t)(b * T_ + row0    )) * E_ + h * DH_;
    size_t ob1 = ((size_t)(b * T_ + row0 + 8)) * E_ + h * DH_;
    #pragma unroll
    for (int n = 0; n < 4; n++) {
        int c = n * 8 + 2 * t;
        *reinterpret_cast<float2*>(&att[ob0 + c]) =
            make_float2(o[n][0] * inv0, o[n][1] * inv0);
        *reinterpret_cast<float2*>(&att[ob1 + c]) =
            make_float2(o[n][2] * inv1, o[n][3] * inv1);
    }
}

// ---------------------------------------------------------------------------
// Launch
// ---------------------------------------------------------------------------
extern "C" void kernel_launch(void* const* d_in, const int* in_sizes, int n_in,
                              void* d_out, int out_size)
{
    const float* x    = (const float*)d_in[0];   // [8,2048,256]
    const float* Wqkv = (const float*)d_in[1];   // [256,768]
    const float* bqkv = (const float*)d_in[2];   // [768]
    const float* Wout = (const float*)d_in[3];   // [256,256]
    const float* bout = (const float*)d_in[4];   // [256]
    float* out = (float*)d_out;                  // [8,2048,256]
    (void)in_sizes; (void)n_in; (void)out_size;

    float* qkv = nullptr;
    float* att = nullptr;
    cudaGetSymbolAddress((void**)&qkv, g_qkv);
    cudaGetSymbolAddress((void**)&att, g_att);

    // 0) RoPE table (tiny; deterministic every call)
    rope_table_kernel<<<(T_ * 16 + 255) / 256, 256>>>();

    // 1) QKV projection + bias
    {
        dim3 grid(N3_ / 64, M_ / 64);   // (12, 256)
        sgemm_bias_kernel<<<grid, 256>>>(x, Wqkv, bqkv, qkv, M_, N3_, E_);
    }

    // 2) RoPE on q,k (table lookup)
    {
        int total = M_ * 2 * H_ * (DH_ / 2);
        rope_kernel<<<(total + 255) / 256, 256>>>(qkv);
    }

    // 3) Causal flash attention (tensor cores)
    {
        dim3 grid(T_ / 128, B_ * H_);   // (16, 64)
        flash_attn_tc_kernel<<<grid, 256>>>(qkv, att);
    }

    // 4) Output projection + bias
    {
        dim3 grid(E_ / 64, M_ / 64);    // (4, 256)
        sgemm_bias_kernel<<<grid, 256>>>(att, Wout, bout, out, M_, E_, E_);
    }
}